// round 13
// baseline (speedup 1.0000x reference)
#include <cuda_runtime.h>

#define BB 16
#define NNODE 512
#define DD 12
#define HIDN 32
#define NHEAD 4
#define CDIM 8

typedef unsigned long long ull;

// ---------------- scratch (no allocs allowed) ----------------
__device__ __align__(16) float g_buf  [BB*NNODE*HIDN];
__device__ __align__(16) float as_buf [BB*NNODE*NHEAD];
__device__ __align__(16) float ad_buf [BB*NNODE*NHEAD];
__device__ __align__(16) float ti_buf [BB*NNODE*HIDN];   // ti + b1 folded, row-major [node][32]
__device__ __align__(16) float tjT_buf[BB*HIDN*NNODE];   // transposed: [(b*16+p)*512 + j] ull pairs
__device__ __align__(16) float pi_buf [BB*NNODE];        // 0.5 * sum_h w2[h]*ti'[node][h]
__device__ __align__(16) float pj_buf [BB*NNODE];        // 0.5 * sum_h w2[h]*tj [node][h]

// ---------------- f32x2 helpers (Blackwell packed fp32) ----------------
__device__ __forceinline__ ull add2(ull a, ull b){ ull r; asm("add.rn.f32x2 %0, %1, %2;" : "=l"(r) : "l"(a), "l"(b)); return r; }
__device__ __forceinline__ ull fma2(ull a, ull b, ull c){ ull r; asm("fma.rn.f32x2 %0, %1, %2, %3;" : "=l"(r) : "l"(a), "l"(b), "l"(c)); return r; }
__device__ __forceinline__ ull pack2(float x, float y){
    ull r; asm("mov.b64 %0, {%1, %2};" : "=l"(r) : "r"(__float_as_uint(x)), "r"(__float_as_uint(y))); return r;
}
__device__ __forceinline__ float2 unpack2(ull v){
    unsigned lo, hi; asm("mov.b64 {%0, %1}, %2;" : "=r"(lo), "=r"(hi) : "l"(v));
    return make_float2(__uint_as_float(lo), __uint_as_float(hi));
}
__device__ __forceinline__ float ex2f(float x){ float r; asm("ex2.approx.f32 %0, %1;" : "=f"(r) : "f"(x)); return r; }

// ================= pad kernel (ncu capture phase-shift) =================
__global__ void pad_k() {}

// ================= K1: per-node embeddings h -> g, a_s, a_d =================
// 128 blocks x 256 threads; 64 nodes/block, 8 nodes/warp, lane = output column k.
// Weights register-resident; single 0.86-full wave; setup amortized over 8 nodes.
__global__ void __launch_bounds__(256) k1_embed(
    const float* __restrict__ x, const float* __restrict__ Wp, const float* __restrict__ bp,
    const float* __restrict__ Wg, const float* __restrict__ att_src, const float* __restrict__ att_dst)
{
    __shared__ float xs  [64*12];
    __shared__ float Wp_s[32*12];
    __shared__ float Wg_s[32*36];       // pad 36: 16B-aligned rows
    __shared__ float hs  [2][8][32];    // double-buffered per-warp h rows

    int t = threadIdx.x, lane = t & 31, w = t >> 5;
    int nb = blockIdx.x * 64;

    for (int i = t; i < 64*12; i += 256) xs[i] = x[(size_t)nb*12 + i];
    for (int i = t; i < 32*12; i += 256) Wp_s[i] = Wp[i];
    for (int i = t; i < 32*32; i += 256) Wg_s[(i >> 5)*36 + (i & 31)] = Wg[i];
    __syncthreads();

    // per-thread weight registers (one-time LDS)
    float wp[12], wg[32];
#pragma unroll
    for (int c = 0; c < 3; ++c) {
        float4 v = *(const float4*)&Wp_s[lane*12 + c*4];
        wp[c*4] = v.x; wp[c*4+1] = v.y; wp[c*4+2] = v.z; wp[c*4+3] = v.w;
    }
#pragma unroll
    for (int c = 0; c < 8; ++c) {
        float4 v = *(const float4*)&Wg_s[lane*36 + c*4];
        wg[c*4] = v.x; wg[c*4+1] = v.y; wg[c*4+2] = v.z; wg[c*4+3] = v.w;
    }
    float bpk = bp[lane], ask = att_src[lane], adk = att_dst[lane];

#pragma unroll
    for (int it = 0; it < 8; ++it) {
        int nl = w*8 + it;
        int node = nb + nl;

        // phase 1: h[node][lane]
        const float4* xp = (const float4*)&xs[nl*12];   // broadcast LDS.128
        float4 x0 = xp[0], x1 = xp[1], x2 = xp[2];
        float hk = bpk;
        hk = fmaf(x0.x, wp[0],  hk); hk = fmaf(x0.y, wp[1],  hk);
        hk = fmaf(x0.z, wp[2],  hk); hk = fmaf(x0.w, wp[3],  hk);
        hk = fmaf(x1.x, wp[4],  hk); hk = fmaf(x1.y, wp[5],  hk);
        hk = fmaf(x1.z, wp[6],  hk); hk = fmaf(x1.w, wp[7],  hk);
        hk = fmaf(x2.x, wp[8],  hk); hk = fmaf(x2.y, wp[9],  hk);
        hk = fmaf(x2.z, wp[10], hk); hk = fmaf(x2.w, wp[11], hk);
        hk = fmaxf(hk, 0.f);

        hs[it & 1][w][lane] = hk;
        __syncwarp();

        // phase 2: g[node][lane] from register weights + broadcast h
        const float4* hp = (const float4*)hs[it & 1][w];
        float g = 0.f;
#pragma unroll
        for (int c = 0; c < 8; ++c) {
            float4 hv = hp[c];                           // broadcast LDS.128
            g = fmaf(hv.x, wg[4*c+0], g);
            g = fmaf(hv.y, wg[4*c+1], g);
            g = fmaf(hv.z, wg[4*c+2], g);
            g = fmaf(hv.w, wg[4*c+3], g);
        }
        g_buf[(size_t)node*HIDN + lane] = g;             // coalesced STG

        float asum = g * ask, adsum = g * adk;           // head = lane>>3
        asum  += __shfl_xor_sync(0xffffffffu, asum, 1);
        asum  += __shfl_xor_sync(0xffffffffu, asum, 2);
        asum  += __shfl_xor_sync(0xffffffffu, asum, 4);
        adsum += __shfl_xor_sync(0xffffffffu, adsum, 1);
        adsum += __shfl_xor_sync(0xffffffffu, adsum, 2);
        adsum += __shfl_xor_sync(0xffffffffu, adsum, 4);
        if ((lane & 7) == 0) {
            as_buf[node*NHEAD + (lane >> 3)] = asum;
            ad_buf[node*NHEAD + (lane >> 3)] = adsum;
        }
    }
}

// ================= K2: attention softmax + h_gnn + ti/tjT + pi/pj =================
// Grid (32 j-tiles x 16 b), 256 threads, static smem ~39.4KB.
// Warp w = private 64-i segment; covers 16 j (2 j-groups per lane).
// i-loop 2-wide software pipeline: 4 LDG.128 batched (MLP=4) before compute.
__global__ void __launch_bounds__(256) k2_attn(
    const int* __restrict__ adj, const float* __restrict__ bias_g,
    const float* __restrict__ W1, const float* __restrict__ b1,
    const float* __restrict__ w2)
{
    __shared__ float    part_s[8*16*4*9];      // seg, j, h, (den + 8 num)
    __shared__ float    asT_s[4*520];          // a_s transposed
    __shared__ unsigned mask_s[NNODE];         // (adj|eye) 16-bit column masks
    __shared__ float    hg_s[16*33];
    __shared__ float    w2_s[HIDN];
    __shared__ float    W1T_s[32*65];          // W1T[d][o], pad 65

    int t  = threadIdx.x;
    int b  = blockIdx.y;
    int j0 = blockIdx.x * 16;
    int w = t >> 5, lane = t & 31;

    const float* asp = as_buf + (size_t)b * NNODE * NHEAD;
    for (int idx = t; idx < NNODE*NHEAD; idx += 256) {
        int i = idx >> 2, h = idx & 3;
        asT_s[h*520 + i] = asp[idx];
    }
    if (t < HIDN) w2_s[t] = w2[t];

    for (int idx = t; idx < 32*64; idx += 256) {
        int r = idx >> 6, c = idx & 63;     // W1[r][c], coalesced
        int d = (c < 32) ? c : (c - 32);
        int o = (c < 32) ? r : (r + 32);
        W1T_s[d*65 + o] = W1[idx];
    }

    // mask: warp w builds its own i-segment [64w, 64w+64); 2 rows per ballot.
    {
        int jl = lane & 15, ip = lane >> 4;   // lanes 0-15: row i, 16-31: row i+1
        const int* ab = adj + (size_t)b * NNODE * NNODE + j0 + jl;
        int base = w * 64;
#pragma unroll
        for (int c = 0; c < 8; ++c) {
            int i = base + c*8;
            int a0 = ab[(size_t)(i+0+ip) * NNODE];
            int a1 = ab[(size_t)(i+2+ip) * NNODE];
            int a2 = ab[(size_t)(i+4+ip) * NNODE];
            int a3 = ab[(size_t)(i+6+ip) * NNODE];
            unsigned m0 = __ballot_sync(0xffffffffu, (a0 != 0) || (i+0+ip == j0 + jl));
            unsigned m1 = __ballot_sync(0xffffffffu, (a1 != 0) || (i+2+ip == j0 + jl));
            unsigned m2 = __ballot_sync(0xffffffffu, (a2 != 0) || (i+4+ip == j0 + jl));
            unsigned m3 = __ballot_sync(0xffffffffu, (a3 != 0) || (i+6+ip == j0 + jl));
            if (lane == 0) {
                mask_s[i+0] = m0 & 0xFFFFu; mask_s[i+1] = m0 >> 16;
                mask_s[i+2] = m1 & 0xFFFFu; mask_s[i+3] = m1 >> 16;
                mask_s[i+4] = m2 & 0xFFFFu; mask_s[i+5] = m2 >> 16;
                mask_s[i+6] = m3 & 0xFFFFu; mask_s[i+7] = m3 >> 16;
            }
        }
    }
    __syncthreads();

    int h = lane & 3, jslot = lane >> 2;   // jslot 0..7

    float adv[2];
#pragma unroll
    for (int g = 0; g < 2; ++g)
        adv[g] = ad_buf[((size_t)(b*NNODE) + j0 + g*8 + jslot)*NHEAD + h];
    unsigned bit0 = 1u << jslot;

    float den[2] = {0,0};
    ull num[8];
#pragma unroll
    for (int q = 0; q < 8; ++q) num[q] = 0ull;

    const ulonglong2* gq2 = (const ulonglong2*)(g_buf + (size_t)b * NNODE * HIDN);

    const float C06 = 0.8656170246f;   // 0.6 * log2(e)
    const float C04 = 0.5770780164f;   // 0.4 * log2(e)

    int ibeg = w * 64, iend = ibeg + 64;
#pragma unroll 2
    for (int i = ibeg; i < iend; i += 2) {
        // batched loads for two i's: MLP=4 on the L2 path
        ulonglong2 ga0 = gq2[(i+0)*8 + h*2];
        ulonglong2 gb0 = gq2[(i+0)*8 + h*2 + 1];
        ulonglong2 ga1 = gq2[(i+1)*8 + h*2];
        ulonglong2 gb1 = gq2[(i+1)*8 + h*2 + 1];
        float asv0  = asT_s[h*520 + i];
        float asv1  = asT_s[h*520 + i + 1];
        unsigned mw0 = mask_s[i];
        unsigned mw1 = mask_s[i+1];
#pragma unroll
        for (int g = 0; g < 2; ++g) {
            float s0 = asv0 + adv[g];
            float s1 = asv1 + adv[g];
            float arg0 = fmaf(C04, fabsf(s0), C06*s0);  // log2e * leakyrelu(s, 0.2)
            float arg1 = fmaf(C04, fabsf(s1), C06*s1);
            float e0 = ex2f(arg0);
            float e1 = ex2f(arg1);
            e0 = (mw0 & (bit0 << (8*g))) ? e0 : 0.f;
            e1 = (mw1 & (bit0 << (8*g))) ? e1 : 0.f;
            den[g] += e0 + e1;
            ull e20 = pack2(e0, e0);
            ull e21 = pack2(e1, e1);
            num[4*g+0] = fma2(e20, ga0.x, num[4*g+0]);
            num[4*g+1] = fma2(e20, ga0.y, num[4*g+1]);
            num[4*g+2] = fma2(e20, gb0.x, num[4*g+2]);
            num[4*g+3] = fma2(e20, gb0.y, num[4*g+3]);
            num[4*g+0] = fma2(e21, ga1.x, num[4*g+0]);
            num[4*g+1] = fma2(e21, ga1.y, num[4*g+1]);
            num[4*g+2] = fma2(e21, gb1.x, num[4*g+2]);
            num[4*g+3] = fma2(e21, gb1.y, num[4*g+3]);
        }
    }
#pragma unroll
    for (int g = 0; g < 2; ++g) {
        float* pp = part_s + ((w*16 + g*8 + jslot)*4 + h)*9;
        pp[0] = den[g];
#pragma unroll
        for (int c = 0; c < 4; ++c) {
            float2 f = unpack2(num[4*g+c]); pp[1+2*c] = f.x; pp[2+2*c] = f.y;
        }
    }
    __syncthreads();

    // reduce 8 i-segments -> h_gnn[j][32] (+bias_g)
    if (t < 64) {
        int jl = t >> 2, hh = t & 3;
        float dn = 0.f, nm[8] = {0,0,0,0,0,0,0,0};
#pragma unroll
        for (int q = 0; q < 8; ++q) {
            const float* pp = part_s + ((q*16 + jl)*4 + hh)*9;
            dn += pp[0];
#pragma unroll
            for (int c = 0; c < 8; ++c) nm[c] += pp[1+c];
        }
        float inv = __fdividef(1.f, dn);    // diag always unmasked => dn > 0
#pragma unroll
        for (int c = 0; c < 8; ++c)
            hg_s[jl*33 + hh*8 + c] = fmaf(nm[c], inv, bias_g[hh*8 + c]);
    }
    __syncthreads();

    // ti' = h_gnn@W1[:,:32]^T + b1 ; tj = h_gnn@W1[:,32:]^T (transposed layout);
    // pi/pj via warp reduction (warp-uniform j & half).
    for (int k = t; k < 16*64; k += 256) {
        int j = k >> 6, o = k & 63;
        float acc = (o < 32) ? b1[o] : 0.f;
#pragma unroll
        for (int d = 0; d < 32; ++d) acc = fmaf(hg_s[j*33 + d], W1T_s[d*65 + o], acc);
        size_t node = (size_t)(b*NNODE) + j0 + j;
        if (o < 32) {
            ti_buf[node*32 + o] = acc;
        } else {
            int oo = o - 32;
            tjT_buf[(((size_t)b*16 + (oo>>1))*NNODE + j0 + j)*2 + (oo & 1)] = acc;
        }
        float v = acc * w2_s[o & 31];
        v += __shfl_xor_sync(0xffffffffu, v, 16);
        v += __shfl_xor_sync(0xffffffffu, v, 8);
        v += __shfl_xor_sync(0xffffffffu, v, 4);
        v += __shfl_xor_sync(0xffffffffu, v, 2);
        v += __shfl_xor_sync(0xffffffffu, v, 1);
        if (lane == 0) {
            if (o < 32) pi_buf[node] = 0.5f * v;
            else        pj_buf[node] = 0.5f * v;
        }
    }
}

// ================= K4: pairwise edge scorer =================
// sum_h w2*relu(ti+tj) = pi + pj + sum_h (w2/2)*|ti+tj| ; |.| = packed AND.
// Dual i-chains; K4_IT=32 -> grid 512 (finer wave granularity).
#define K4_IT 32
__global__ void __launch_bounds__(256, 2) k4_score(
    const int* __restrict__ adj, const float* __restrict__ w2,
    const float* __restrict__ b2, float* __restrict__ out)
{
    __shared__ ull   ti_s[K4_IT*16];
    __shared__ float pi_s[K4_IT];
    __shared__ ull   w2p_s[16];
    int t = threadIdx.x, lane = t & 31, w = t >> 5;
    int b  = blockIdx.z;
    int i0 = blockIdx.y * K4_IT;
    int j  = blockIdx.x * 256 + w*32 + lane;

    const ull* tiu = (const ull*)ti_buf + ((size_t)(b*NNODE) + i0)*16;
    for (int idx = t; idx < K4_IT*16; idx += 256) ti_s[idx] = tiu[idx];
    if (t < K4_IT) pi_s[t] = pi_buf[(size_t)(b*NNODE) + i0 + t];
    if (t < 16)    w2p_s[t] = pack2(0.5f*w2[2*t], 0.5f*w2[2*t+1]);
    __syncthreads();

    ull tj2[16], w2r[16];
    const ull* tjp = (const ull*)tjT_buf;
#pragma unroll
    for (int p = 0; p < 16; ++p) tj2[p] = tjp[((size_t)b*16 + p)*NNODE + j];
#pragma unroll
    for (int p = 0; p < 16; ++p) w2r[p] = w2p_s[p];
    float pj  = pj_buf[(size_t)(b*NNODE) + j];
    float b2v = b2[0] + pj;

    const int* arow = adj + ((size_t)(b*NNODE) + i0)*NNODE + j;
    float*     orow = out + ((size_t)(b*NNODE) + i0)*NNODE + j;
    const ull ABS2 = 0x7FFFFFFF7FFFFFFFull;

    for (int ib = 0; ib < K4_IT; ib += 4) {
        int av[4];
#pragma unroll
        for (int k = 0; k < 4; ++k) av[k] = arow[(size_t)(ib + k) * NNODE];

#pragma unroll
        for (int kk = 0; kk < 2; ++kk) {
            int iA = ib + kk*2, iB = iA + 1;
            const ulonglong2* tpA = (const ulonglong2*)&ti_s[iA*16];
            const ulonglong2* tpB = (const ulonglong2*)&ti_s[iB*16];
            ull aA0 = 0, aA1 = 0, aB0 = 0, aB1 = 0;
#pragma unroll
            for (int q = 0; q < 8; ++q) {
                ulonglong2 tvA = tpA[q];                  // LDS.128 broadcast (chain A)
                ulonglong2 tvB = tpB[q];                  // LDS.128 broadcast (chain B)
                ull sA0 = add2(tj2[2*q],   tvA.x) & ABS2; // packed |ti+tj|
                ull sB0 = add2(tj2[2*q],   tvB.x) & ABS2;
                ull sA1 = add2(tj2[2*q+1], tvA.y) & ABS2;
                ull sB1 = add2(tj2[2*q+1], tvB.y) & ABS2;
                aA0 = fma2(w2r[2*q],   sA0, aA0);
                aB0 = fma2(w2r[2*q],   sB0, aB0);
                aA1 = fma2(w2r[2*q+1], sA1, aA1);
                aB1 = fma2(w2r[2*q+1], sB1, aB1);
            }
            float2 sfA = unpack2(add2(aA0, aA1));
            float2 sfB = unpack2(add2(aB0, aB1));
            float logitA = sfA.x + sfA.y + pi_s[iA] + b2v;
            float logitB = sfB.x + sfB.y + pi_s[iB] + b2v;
            float eA  = ex2f(-1.4426950409f * logitA);    // exp(-logit)
            float eB  = ex2f(-1.4426950409f * logitB);
            float scA = __fdividef(1.f, 1.f + eA);
            float scB = __fdividef(1.f, 1.f + eB);

            orow[(size_t)iA * NNODE] = (av[kk*2]   != 0 && (i0 + iA) != j) ? scA : 0.f;
            orow[(size_t)iB * NNODE] = (av[kk*2+1] != 0 && (i0 + iB) != j) ? scB : 0.f;
        }
    }
}

// ================= launch =================
extern "C" void kernel_launch(void* const* d_in, const int* in_sizes, int n_in,
                              void* d_out, int out_size)
{
    const float* x        = (const float*)d_in[0];
    const int*   adj      = (const int*)  d_in[1];
    const float* Wp       = (const float*)d_in[2];
    const float* bp       = (const float*)d_in[3];
    const float* Wg       = (const float*)d_in[4];
    const float* att_src  = (const float*)d_in[5];
    const float* att_dst  = (const float*)d_in[6];
    const float* bias_g   = (const float*)d_in[7];
    const float* W1       = (const float*)d_in[8];
    const float* b1       = (const float*)d_in[9];
    const float* w2       = (const float*)d_in[10];
    const float* b2       = (const float*)d_in[11];
    float* out = (float*)d_out;

    // two pads: shift the ncu -s 5 capture slot onto k2 (first profile of its
    // current form)
    pad_k<<<1, 32>>>();
    pad_k<<<1, 32>>>();

    k1_embed<<<BB*NNODE/64, 256>>>(x, Wp, bp, Wg, att_src, att_dst);

    k2_attn<<<dim3(NNODE/16, BB), 256>>>(adj, bias_g, W1, b1, w2);

    k4_score<<<dim3(2, NNODE/K4_IT, BB), 256>>>(adj, w2, b2, out);
}

// round 14
// speedup vs baseline: 1.0810x; 1.0810x over previous
#include <cuda_runtime.h>

#define BB 16
#define NNODE 512
#define DD 12
#define HIDN 32
#define NHEAD 4
#define CDIM 8

typedef unsigned long long ull;

// ---------------- scratch (no allocs allowed) ----------------
__device__ __align__(16) float g_buf  [BB*NNODE*HIDN];
__device__ __align__(16) float as_buf [BB*NNODE*NHEAD];
__device__ __align__(16) float ad_buf [BB*NNODE*NHEAD];
__device__ __align__(16) float ti_buf [BB*NNODE*HIDN];   // ti + b1 folded, row-major [node][32]
__device__ __align__(16) float tjT_buf[BB*HIDN*NNODE];   // transposed: [(b*16+p)*512 + j] ull pairs
__device__ __align__(16) float pi_buf [BB*NNODE];        // 0.5 * sum_h w2[h]*ti'[node][h]
__device__ __align__(16) float pj_buf [BB*NNODE];        // 0.5 * sum_h w2[h]*tj [node][h]

// ---------------- f32x2 helpers (Blackwell packed fp32) ----------------
__device__ __forceinline__ ull add2(ull a, ull b){ ull r; asm("add.rn.f32x2 %0, %1, %2;" : "=l"(r) : "l"(a), "l"(b)); return r; }
__device__ __forceinline__ ull fma2(ull a, ull b, ull c){ ull r; asm("fma.rn.f32x2 %0, %1, %2, %3;" : "=l"(r) : "l"(a), "l"(b), "l"(c)); return r; }
__device__ __forceinline__ ull pack2(float x, float y){
    ull r; asm("mov.b64 %0, {%1, %2};" : "=l"(r) : "r"(__float_as_uint(x)), "r"(__float_as_uint(y))); return r;
}
__device__ __forceinline__ float2 unpack2(ull v){
    unsigned lo, hi; asm("mov.b64 {%0, %1}, %2;" : "=r"(lo), "=r"(hi) : "l"(v));
    return make_float2(__uint_as_float(lo), __uint_as_float(hi));
}
__device__ __forceinline__ float ex2f(float x){ float r; asm("ex2.approx.f32 %0, %1;" : "=f"(r) : "f"(x)); return r; }

// ================= K1: per-node embeddings h -> g, a_s, a_d =================
// (R12 form, measured 7.97us) 256 blocks x 256 threads; 32 nodes/block,
// 4 nodes/warp, lane = output column k. Weights register-resident.
__global__ void __launch_bounds__(256) k1_embed(
    const float* __restrict__ x, const float* __restrict__ Wp, const float* __restrict__ bp,
    const float* __restrict__ Wg, const float* __restrict__ att_src, const float* __restrict__ att_dst)
{
    __shared__ float xs  [32*12];
    __shared__ float Wp_s[32*12];
    __shared__ float Wg_s[32*36];       // pad 36: 16B-aligned rows
    __shared__ float hs  [2][8][32];    // double-buffered per-warp h rows

    int t = threadIdx.x, lane = t & 31, w = t >> 5;
    int nb = blockIdx.x * 32;

    for (int i = t; i < 32*12; i += 256) { xs[i] = x[(size_t)nb*12 + i]; Wp_s[i] = Wp[i]; }
    for (int i = t; i < 32*32; i += 256) Wg_s[(i >> 5)*36 + (i & 31)] = Wg[i];
    __syncthreads();

    float wp[12], wg[32];
#pragma unroll
    for (int c = 0; c < 3; ++c) {
        float4 v = *(const float4*)&Wp_s[lane*12 + c*4];
        wp[c*4] = v.x; wp[c*4+1] = v.y; wp[c*4+2] = v.z; wp[c*4+3] = v.w;
    }
#pragma unroll
    for (int c = 0; c < 8; ++c) {
        float4 v = *(const float4*)&Wg_s[lane*36 + c*4];
        wg[c*4] = v.x; wg[c*4+1] = v.y; wg[c*4+2] = v.z; wg[c*4+3] = v.w;
    }
    float bpk = bp[lane], ask = att_src[lane], adk = att_dst[lane];

#pragma unroll
    for (int it = 0; it < 4; ++it) {
        int nl = w*4 + it;
        int node = nb + nl;

        const float4* xp = (const float4*)&xs[nl*12];   // broadcast LDS.128
        float4 x0 = xp[0], x1 = xp[1], x2 = xp[2];
        float hk = bpk;
        hk = fmaf(x0.x, wp[0],  hk); hk = fmaf(x0.y, wp[1],  hk);
        hk = fmaf(x0.z, wp[2],  hk); hk = fmaf(x0.w, wp[3],  hk);
        hk = fmaf(x1.x, wp[4],  hk); hk = fmaf(x1.y, wp[5],  hk);
        hk = fmaf(x1.z, wp[6],  hk); hk = fmaf(x1.w, wp[7],  hk);
        hk = fmaf(x2.x, wp[8],  hk); hk = fmaf(x2.y, wp[9],  hk);
        hk = fmaf(x2.z, wp[10], hk); hk = fmaf(x2.w, wp[11], hk);
        hk = fmaxf(hk, 0.f);

        hs[it & 1][w][lane] = hk;
        __syncwarp();

        const float4* hp = (const float4*)hs[it & 1][w];
        float g = 0.f;
#pragma unroll
        for (int c = 0; c < 8; ++c) {
            float4 hv = hp[c];                           // broadcast LDS.128
            g = fmaf(hv.x, wg[4*c+0], g);
            g = fmaf(hv.y, wg[4*c+1], g);
            g = fmaf(hv.z, wg[4*c+2], g);
            g = fmaf(hv.w, wg[4*c+3], g);
        }
        g_buf[(size_t)node*HIDN + lane] = g;             // coalesced STG

        float asum = g * ask, adsum = g * adk;           // head = lane>>3
        asum  += __shfl_xor_sync(0xffffffffu, asum, 1);
        asum  += __shfl_xor_sync(0xffffffffu, asum, 2);
        asum  += __shfl_xor_sync(0xffffffffu, asum, 4);
        adsum += __shfl_xor_sync(0xffffffffu, adsum, 1);
        adsum += __shfl_xor_sync(0xffffffffu, adsum, 2);
        adsum += __shfl_xor_sync(0xffffffffu, adsum, 4);
        if ((lane & 7) == 0) {
            as_buf[node*NHEAD + (lane >> 3)] = asum;
            ad_buf[node*NHEAD + (lane >> 3)] = adsum;
        }
    }
}

// ================= K2: attention softmax + h_gnn + ti/tjT + pi/pj =================
// (R11/R6 form) 512 threads, dynamic smem ~94.5KB (2 blocks/SM).
// Warp w = private 32-i segment; covers ALL 32 j (4 j-groups per lane).
#define SM_PART  0                          // 16*32*4*9*4   = 73728
#define SM_AST   73728                      // 4*520*4       = 8320
#define SM_MASK  82048                      // 512*4         = 2048
#define SM_HG    84096                      // 32*33*4       = 4224
#define SM_W2    88320                      // 128
#define SM_W1T   88448                      // 32*65*4       = 8320
#define SM_TOTAL 96768

__global__ void __launch_bounds__(512, 2) k2_attn(
    const int* __restrict__ adj, const float* __restrict__ bias_g,
    const float* __restrict__ W1, const float* __restrict__ b1,
    const float* __restrict__ w2)
{
    extern __shared__ char sm[];
    float*    part_s = (float*) (sm + SM_PART);
    float*    asT_s  = (float*) (sm + SM_AST);
    unsigned* mask_s = (unsigned*)(sm + SM_MASK);
    float*    hg_s   = (float*) (sm + SM_HG);
    float*    w2_s   = (float*) (sm + SM_W2);
    float*    W1T_s  = (float*) (sm + SM_W1T);

    int t  = threadIdx.x;
    int b  = blockIdx.y;
    int j0 = blockIdx.x * 32;
    int w = t >> 5, lane = t & 31;

    const float* asp = as_buf + (size_t)b * NNODE * NHEAD;
    for (int idx = t; idx < NNODE*NHEAD; idx += 512) {
        int i = idx >> 2, h = idx & 3;
        asT_s[h*520 + i] = asp[idx];
    }
    if (t < HIDN) w2_s[t] = w2[t];

    for (int idx = t; idx < 32*64; idx += 512) {
        int r = idx >> 6, c = idx & 63;     // W1[r][c], coalesced read
        int d = (c < 32) ? c : (c - 32);
        int o = (c < 32) ? r : (r + 32);
        W1T_s[d*65 + o] = W1[idx];
    }

    {
        const int* ab = adj + (size_t)b * NNODE * NNODE + j0 + lane;
        int base = w * 32;
#pragma unroll
        for (int c = 0; c < 8; ++c) {
            int i = base + c*4;
            int a0 = ab[(size_t)(i+0) * NNODE];
            int a1 = ab[(size_t)(i+1) * NNODE];
            int a2 = ab[(size_t)(i+2) * NNODE];
            int a3 = ab[(size_t)(i+3) * NNODE];
            unsigned m0 = __ballot_sync(0xffffffffu, (a0 != 0) || (i+0 == j0 + lane));
            unsigned m1 = __ballot_sync(0xffffffffu, (a1 != 0) || (i+1 == j0 + lane));
            unsigned m2 = __ballot_sync(0xffffffffu, (a2 != 0) || (i+2 == j0 + lane));
            unsigned m3 = __ballot_sync(0xffffffffu, (a3 != 0) || (i+3 == j0 + lane));
            if (lane == 0) { mask_s[i] = m0; mask_s[i+1] = m1; mask_s[i+2] = m2; mask_s[i+3] = m3; }
        }
    }
    __syncthreads();

    int h = lane & 3, jslot = lane >> 2;

    float adv[4];
#pragma unroll
    for (int g = 0; g < 4; ++g)
        adv[g] = ad_buf[((size_t)(b*NNODE) + j0 + g*8 + jslot)*NHEAD + h];
    unsigned bit0 = 1u << jslot;

    float den[4] = {0,0,0,0};
    ull num[16];
#pragma unroll
    for (int q = 0; q < 16; ++q) num[q] = 0ull;

    const ulonglong2* gq2 = (const ulonglong2*)(g_buf + (size_t)b * NNODE * HIDN);

    const float C06 = 0.8656170246f;   // 0.6 * log2(e)
    const float C04 = 0.5770780164f;   // 0.4 * log2(e)

    int ibeg = w * 32, iend = ibeg + 32;
#pragma unroll 2
    for (int i = ibeg; i < iend; ++i) {
        float asv   = asT_s[h*520 + i];
        unsigned mw = mask_s[i];
        ulonglong2 ga = gq2[i*8 + h*2];       // LDG.128, one L2 line per warp-i
        ulonglong2 gb = gq2[i*8 + h*2 + 1];
#pragma unroll
        for (int g = 0; g < 4; ++g) {
            float s = asv + adv[g];
            float arg = fmaf(C04, fabsf(s), C06*s);  // log2e * leakyrelu(s, 0.2)
            float e = ex2f(arg);
            e = (mw & (bit0 << (8*g))) ? e : 0.f;
            den[g] += e;
            ull e2 = pack2(e, e);
            num[4*g+0] = fma2(e2, ga.x, num[4*g+0]);
            num[4*g+1] = fma2(e2, ga.y, num[4*g+1]);
            num[4*g+2] = fma2(e2, gb.x, num[4*g+2]);
            num[4*g+3] = fma2(e2, gb.y, num[4*g+3]);
        }
    }
#pragma unroll
    for (int g = 0; g < 4; ++g) {
        float* pp = part_s + ((w*32 + g*8 + jslot)*4 + h)*9;
        pp[0] = den[g];
#pragma unroll
        for (int c = 0; c < 4; ++c) {
            float2 f = unpack2(num[4*g+c]); pp[1+2*c] = f.x; pp[2+2*c] = f.y;
        }
    }
    __syncthreads();

    if (t < 128) {
        int jl = t >> 2, hh = t & 3;
        float dn = 0.f, nm[8] = {0,0,0,0,0,0,0,0};
#pragma unroll
        for (int q = 0; q < 16; ++q) {
            const float* pp = part_s + ((q*32 + jl)*4 + hh)*9;
            dn += pp[0];
#pragma unroll
            for (int c = 0; c < 8; ++c) nm[c] += pp[1+c];
        }
        float inv = __fdividef(1.f, dn);    // diag always unmasked => dn > 0
#pragma unroll
        for (int c = 0; c < 8; ++c)
            hg_s[jl*33 + hh*8 + c] = fmaf(nm[c], inv, bias_g[hh*8 + c]);
    }
    __syncthreads();

    for (int k = t; k < 32*64; k += 512) {
        int j = k >> 6, o = k & 63;
        float acc = (o < 32) ? b1[o] : 0.f;
#pragma unroll
        for (int d = 0; d < 32; ++d) acc = fmaf(hg_s[j*33 + d], W1T_s[d*65 + o], acc);
        size_t node = (size_t)(b*NNODE) + j0 + j;
        if (o < 32) {
            ti_buf[node*32 + o] = acc;
        } else {
            int oo = o - 32;
            tjT_buf[(((size_t)b*16 + (oo>>1))*NNODE + j0 + j)*2 + (oo & 1)] = acc;
        }
        float v = acc * w2_s[o & 31];
        v += __shfl_xor_sync(0xffffffffu, v, 16);
        v += __shfl_xor_sync(0xffffffffu, v, 8);
        v += __shfl_xor_sync(0xffffffffu, v, 4);
        v += __shfl_xor_sync(0xffffffffu, v, 2);
        v += __shfl_xor_sync(0xffffffffu, v, 1);
        if (lane == 0) {
            if (o < 32) pi_buf[node] = 0.5f * v;
            else        pj_buf[node] = 0.5f * v;
        }
    }
}

// ================= K4: pairwise edge scorer =================
// (R11 form) sum_h w2*relu(ti+tj) = pi + pj + sum_h (w2/2)*|ti+tj|.
// Dual i-chains; K4_IT=32 -> grid 512; adj prefetched depth-4.
#define K4_IT 32
__global__ void __launch_bounds__(256, 2) k4_score(
    const int* __restrict__ adj, const float* __restrict__ w2,
    const float* __restrict__ b2, float* __restrict__ out)
{
    __shared__ ull   ti_s[K4_IT*16];
    __shared__ float pi_s[K4_IT];
    __shared__ ull   w2p_s[16];
    int t = threadIdx.x, lane = t & 31, w = t >> 5;
    int b  = blockIdx.z;
    int i0 = blockIdx.y * K4_IT;
    int j  = blockIdx.x * 256 + w*32 + lane;

    const ull* tiu = (const ull*)ti_buf + ((size_t)(b*NNODE) + i0)*16;
    for (int idx = t; idx < K4_IT*16; idx += 256) ti_s[idx] = tiu[idx];
    if (t < K4_IT) pi_s[t] = pi_buf[(size_t)(b*NNODE) + i0 + t];
    if (t < 16)    w2p_s[t] = pack2(0.5f*w2[2*t], 0.5f*w2[2*t+1]);
    __syncthreads();

    ull tj2[16], w2r[16];
    const ull* tjp = (const ull*)tjT_buf;
#pragma unroll
    for (int p = 0; p < 16; ++p) tj2[p] = tjp[((size_t)b*16 + p)*NNODE + j];
#pragma unroll
    for (int p = 0; p < 16; ++p) w2r[p] = w2p_s[p];
    float pj  = pj_buf[(size_t)(b*NNODE) + j];
    float b2v = b2[0] + pj;

    const int* arow = adj + ((size_t)(b*NNODE) + i0)*NNODE + j;
    float*     orow = out + ((size_t)(b*NNODE) + i0)*NNODE + j;
    const ull ABS2 = 0x7FFFFFFF7FFFFFFFull;

    for (int ib = 0; ib < K4_IT; ib += 4) {
        int av[4];
#pragma unroll
        for (int k = 0; k < 4; ++k) av[k] = arow[(size_t)(ib + k) * NNODE];

#pragma unroll
        for (int kk = 0; kk < 2; ++kk) {
            int iA = ib + kk*2, iB = iA + 1;
            const ulonglong2* tpA = (const ulonglong2*)&ti_s[iA*16];
            const ulonglong2* tpB = (const ulonglong2*)&ti_s[iB*16];
            ull aA0 = 0, aA1 = 0, aB0 = 0, aB1 = 0;
#pragma unroll
            for (int q = 0; q < 8; ++q) {
                ulonglong2 tvA = tpA[q];                  // LDS.128 broadcast (chain A)
                ulonglong2 tvB = tpB[q];                  // LDS.128 broadcast (chain B)
                ull sA0 = add2(tj2[2*q],   tvA.x) & ABS2; // packed |ti+tj|
                ull sB0 = add2(tj2[2*q],   tvB.x) & ABS2;
                ull sA1 = add2(tj2[2*q+1], tvA.y) & ABS2;
                ull sB1 = add2(tj2[2*q+1], tvB.y) & ABS2;
                aA0 = fma2(w2r[2*q],   sA0, aA0);
                aB0 = fma2(w2r[2*q],   sB0, aB0);
                aA1 = fma2(w2r[2*q+1], sA1, aA1);
                aB1 = fma2(w2r[2*q+1], sB1, aB1);
            }
            float2 sfA = unpack2(add2(aA0, aA1));
            float2 sfB = unpack2(add2(aB0, aB1));
            float logitA = sfA.x + sfA.y + pi_s[iA] + b2v;
            float logitB = sfB.x + sfB.y + pi_s[iB] + b2v;
            float eA  = ex2f(-1.4426950409f * logitA);    // exp(-logit)
            float eB  = ex2f(-1.4426950409f * logitB);
            float scA = __fdividef(1.f, 1.f + eA);
            float scB = __fdividef(1.f, 1.f + eB);

            orow[(size_t)iA * NNODE] = (av[kk*2]   != 0 && (i0 + iA) != j) ? scA : 0.f;
            orow[(size_t)iB * NNODE] = (av[kk*2+1] != 0 && (i0 + iB) != j) ? scB : 0.f;
        }
    }
}

// ================= launch =================
extern "C" void kernel_launch(void* const* d_in, const int* in_sizes, int n_in,
                              void* d_out, int out_size)
{
    const float* x        = (const float*)d_in[0];
    const int*   adj      = (const int*)  d_in[1];
    const float* Wp       = (const float*)d_in[2];
    const float* bp       = (const float*)d_in[3];
    const float* Wg       = (const float*)d_in[4];
    const float* att_src  = (const float*)d_in[5];
    const float* att_dst  = (const float*)d_in[6];
    const float* bias_g   = (const float*)d_in[7];
    const float* W1       = (const float*)d_in[8];
    const float* b1       = (const float*)d_in[9];
    const float* w2       = (const float*)d_in[10];
    const float* b2       = (const float*)d_in[11];
    float* out = (float*)d_out;

    k1_embed<<<BB*NNODE/32, 256>>>(x, Wp, bp, Wg, att_src, att_dst);

    cudaFuncSetAttribute(k2_attn, cudaFuncAttributeMaxDynamicSharedMemorySize, SM_TOTAL);
    k2_attn<<<dim3(NNODE/32, BB), 512, SM_TOTAL>>>(adj, bias_g, W1, b1, w2);

    k4_score<<<dim3(2, NNODE/K4_IT, BB), 256>>>(adj, w2, b2, out);
}